// round 5
// baseline (speedup 1.0000x reference)
#include <cuda_runtime.h>

#define N_NODES 50000
#define N_EDGES 800000
#define F_IN    128
#define H_DIM   64
#define C_OUT   40

// ---------------- scratch (device globals) -----------------------------------
__device__ __align__(16) float g_cat[N_NODES * 192];       // [y1 | xr | xw] per node
__device__ __align__(16) float g_hidden[N_NODES * H_DIM];  // relu(l2norm(conv1))
__device__ __align__(16) float g_z[N_NODES * C_OUT];       // h @ Wl2
__device__ __align__(16) float g_hr[N_NODES * C_OUT];      // h @ Wr2
__device__ __align__(16) int2  g_srcdst[N_EDGES];          // repacked (src,dst)
__device__ __align__(16) int   g_deg[N_NODES];             // in-degree histogram
__device__ __align__(16) int   g_off[N_NODES + 1];         // CSR offsets
__device__ __align__(16) int   g_pos[N_NODES];             // fill cursors (init = off)
__device__ __align__(16) int   g_csr[N_EDGES];             // CSR src lists (by dst)
__device__ int g_is64;                                     // edge dtype flag

// ---------------- helpers ---------------------------------------------------
__device__ __forceinline__ unsigned long long pack2(float a) {
    unsigned long long r;
    asm("mov.b64 %0, {%1, %1};" : "=l"(r) : "f"(a));
    return r;
}
// packed fp32x2 FMA: 2 fp32 FMAs per instruction (sm_100+), exact fp32 numerics
#define FMA2(d, a, b) asm("fma.rn.f32x2 %0, %1, %2, %0;" : "+l"(d) : "l"(a), "l"(b))

// ---------------- dtype probe -------------------------------------------------
// int64 values < 50000 -> every odd 32-bit word is 0; int32 data -> not all zero.
__global__ void k_detect(const int* __restrict__ ei32) {
    __shared__ int s_any;
    if (threadIdx.x == 0) s_any = 0;
    __syncthreads();
    int any = 0;
    for (int s = threadIdx.x; s < 4096; s += 256) {
        int i = s * 195;
        if (ei32[2 * i + 1] != 0) any = 1;
    }
    if (any) atomicOr(&s_any, 1);
    __syncthreads();
    if (threadIdx.x == 0) g_is64 = (s_any == 0);
}

// ---------------- zero degree histogram --------------------------------------
__global__ void k_zero() {
    int i = blockIdx.x * 256 + threadIdx.x;
    if (i < N_NODES) g_deg[i] = 0;
}

// ---------------- repack edges + histogram ------------------------------------
__global__ void k_prep(const int* __restrict__ ei32) {
    int e = blockIdx.x * 256 + threadIdx.x;
    if (e >= N_EDGES) return;
    int2 p;
    if (g_is64) {                        // int64 layout: low word at 2*idx
        p.x = ei32[2 * e];
        p.y = ei32[2 * (N_EDGES + e)];
    } else {                             // int32 layout
        p.x = ei32[e];
        p.y = ei32[N_EDGES + e];
    }
    g_srcdst[e] = p;
    atomicAdd(&g_deg[p.y], 1);
}

// ---------------- exclusive scan (1 block) -> offsets + cursors ----------------
__global__ void k_scan() {
    __shared__ int ssum[1024];
    const int CH = (N_NODES + 1023) / 1024;   // 49
    int t = threadIdx.x;
    int base = t * CH;
    int s = 0;
#pragma unroll
    for (int i = 0; i < CH; i++) {
        int idx = base + i;
        if (idx < N_NODES) s += g_deg[idx];
    }
    ssum[t] = s;
    __syncthreads();
    for (int o = 1; o < 1024; o <<= 1) {
        int v = (t >= o) ? ssum[t - o] : 0;
        __syncthreads();
        ssum[t] += v;
        __syncthreads();
    }
    int run = (t == 0) ? 0 : ssum[t - 1];
#pragma unroll
    for (int i = 0; i < CH; i++) {
        int idx = base + i;
        if (idx < N_NODES) {
            g_off[idx] = run;
            g_pos[idx] = run;
            run += g_deg[idx];
        }
    }
    if (t == 1023) g_off[N_NODES] = ssum[1023];
}

// ---------------- CSR fill ------------------------------------------------------
__global__ void k_fill() {
    int e = blockIdx.x * 256 + threadIdx.x;
    if (e >= N_EDGES) return;
    int2 sd = g_srcdst[e];
    int slot = atomicAdd(&g_pos[sd.y], 1);
    g_csr[slot] = sd.x;
}

// ---------------- GEMM1 fused: g_cat[r][0:192] = x[r] @ [Wl1|Wr1|Wlin_top] ------
// block: 64 rows x 192 cols; 256 threads; thread = 2 rows x 24 cols (f32x2 FMA)
__global__ void __launch_bounds__(256) k_gemm1(const float* __restrict__ x,
                        const float* __restrict__ Wl1,
                        const float* __restrict__ Wr1,
                        const float* __restrict__ Wlin) {
    extern __shared__ float sm[];
    float* xs = sm;               // [64][129]
    float* ws = sm + 64 * 129;    // [128][192]

    int row0 = blockIdx.x * 64;
    int t = threadIdx.x;

    // x tile: 64 rows x 32 float4
    for (int i = t; i < 64 * 32; i += 256) {
        int m = i >> 5, kc = i & 31;
        int r = row0 + m;
        float4 v = (r < N_NODES) ? ((const float4*)x)[r * 32 + kc]
                                 : make_float4(0.f, 0.f, 0.f, 0.f);
        float* d = xs + m * 129 + kc * 4;
        d[0] = v.x; d[1] = v.y; d[2] = v.z; d[3] = v.w;
    }
    // W tile: 128 rows x 48 float4 (cols 0-15:Wl1, 16-31:Wr1, 32-47:Wlin[0:128])
    const float4* wl1 = (const float4*)Wl1;
    const float4* wr1 = (const float4*)Wr1;
    const float4* wli = (const float4*)Wlin;
    for (int i = t; i < 128 * 48; i += 256) {
        int k = i / 48, c = i % 48;
        float4 v = (c < 16) ? wl1[k * 16 + c]
                 : (c < 32) ? wr1[k * 16 + (c - 16)]
                            : wli[k * 16 + (c - 32)];
        ((float4*)(ws + k * 192))[c] = v;
    }
    __syncthreads();

    int rp = t >> 3, cg = t & 7;           // row pair, column group (24 cols)
    const float* xr0 = xs + (2 * rp) * 129;
    const float* xr1 = xr0 + 129;
    unsigned long long acc[24] = {};       // [0..11] row0, [12..23] row1

#pragma unroll 2
    for (int k = 0; k < 128; k++) {
        unsigned long long a0 = pack2(xr0[k]);
        unsigned long long a1 = pack2(xr1[k]);
        const ulonglong2* wp = (const ulonglong2*)(ws + k * 192 + cg * 24);
        ulonglong2 w0 = wp[0], w1 = wp[1], w2 = wp[2];
        ulonglong2 w3 = wp[3], w4 = wp[4], w5 = wp[5];
        FMA2(acc[0],  a0, w0.x); FMA2(acc[1],  a0, w0.y);
        FMA2(acc[2],  a0, w1.x); FMA2(acc[3],  a0, w1.y);
        FMA2(acc[4],  a0, w2.x); FMA2(acc[5],  a0, w2.y);
        FMA2(acc[6],  a0, w3.x); FMA2(acc[7],  a0, w3.y);
        FMA2(acc[8],  a0, w4.x); FMA2(acc[9],  a0, w4.y);
        FMA2(acc[10], a0, w5.x); FMA2(acc[11], a0, w5.y);
        FMA2(acc[12], a1, w0.x); FMA2(acc[13], a1, w0.y);
        FMA2(acc[14], a1, w1.x); FMA2(acc[15], a1, w1.y);
        FMA2(acc[16], a1, w2.x); FMA2(acc[17], a1, w2.y);
        FMA2(acc[18], a1, w3.x); FMA2(acc[19], a1, w3.y);
        FMA2(acc[20], a1, w4.x); FMA2(acc[21], a1, w4.y);
        FMA2(acc[22], a1, w5.x); FMA2(acc[23], a1, w5.y);
    }

    int r0 = row0 + 2 * rp, r1 = r0 + 1;
    float* f0 = (float*)acc;
    float* f1 = (float*)(acc + 12);
    if (r0 < N_NODES) {
        float4* o = (float4*)(g_cat + r0 * 192 + cg * 24);
#pragma unroll
        for (int q = 0; q < 6; q++)
            o[q] = make_float4(f0[4 * q], f0[4 * q + 1], f0[4 * q + 2], f0[4 * q + 3]);
    }
    if (r1 < N_NODES) {
        float4* o = (float4*)(g_cat + r1 * 192 + cg * 24);
#pragma unroll
        for (int q = 0; q < 6; q++)
            o[q] = make_float4(f1[4 * q], f1[4 * q + 1], f1[4 * q + 2], f1[4 * q + 3]);
    }
}

// ---------------- gather1 + node1 epilogue -------------------------------------
// 16 lanes per node; gather y1 rows (g_cat cols 0-63) over CSR, then
// hidden = relu(l2norm(sum/deg + bl1 + xr))
__global__ void k_gather1(const float* __restrict__ bl1) {
    int idx = blockIdx.x * 256 + threadIdx.x;   // exactly N*16 threads
    int node = idx >> 4, j = idx & 15;
    int beg = g_off[node], end = g_off[node + 1];
    const float4* cat4 = (const float4*)g_cat;

    float4 acc = make_float4(0.f, 0.f, 0.f, 0.f);
    for (int e = beg; e < end; e++) {
        int src = g_csr[e];                      // broadcast within 16-lane group
        float4 v = cat4[src * 48 + j];
        acc.x += v.x; acc.y += v.y; acc.z += v.z; acc.w += v.w;
    }
    float inv = 1.0f / fmaxf((float)(end - beg), 1.0f);
    float4 b  = ((const float4*)bl1)[j];
    float4 xr = cat4[node * 48 + 16 + j];
    float4 v;
    v.x = acc.x * inv + b.x + xr.x;
    v.y = acc.y * inv + b.y + xr.y;
    v.z = acc.z * inv + b.z + xr.z;
    v.w = acc.w * inv + b.w + xr.w;
    float ss = v.x * v.x + v.y * v.y + v.z * v.z + v.w * v.w;
    ss += __shfl_xor_sync(0xffffffffu, ss, 8);
    ss += __shfl_xor_sync(0xffffffffu, ss, 4);
    ss += __shfl_xor_sync(0xffffffffu, ss, 2);
    ss += __shfl_xor_sync(0xffffffffu, ss, 1);
    float sc = 1.0f / fmaxf(sqrtf(ss), 1e-12f);
    float4 h;
    h.x = fmaxf(v.x * sc, 0.f);
    h.y = fmaxf(v.y * sc, 0.f);
    h.z = fmaxf(v.z * sc, 0.f);
    h.w = fmaxf(v.w * sc, 0.f);
    ((float4*)g_hidden)[node * 16 + j] = h;
}

// ---------------- GEMM2 (fused): h = relu(xw + hidden@Wh + blin);
//                  z = h@Wl2 ; hr = h@Wr2
__global__ void k_gemm2(const float* __restrict__ Wlin,
                        const float* __restrict__ blin,
                        const float* __restrict__ Wl2,
                        const float* __restrict__ Wr2) {
    extern __shared__ float sm[];
    float* hd = sm;                 // [64][65]
    float* wh = hd + 64 * 65;       // [64][64]
    float* hs = wh + 64 * 64;       // [64][65]
    float* wc = hs + 64 * 65;       // [64][80]

    int row0 = blockIdx.x * 64;
    int t = threadIdx.x;

    for (int i = t; i < 64 * 16; i += 256) {
        int m = i >> 4, kc = i & 15;
        int r = row0 + m;
        float4 v = (r < N_NODES) ? ((const float4*)g_hidden)[r * 16 + kc]
                                 : make_float4(0.f, 0.f, 0.f, 0.f);
        float* d = hd + m * 65 + kc * 4;
        d[0] = v.x; d[1] = v.y; d[2] = v.z; d[3] = v.w;
    }
    const float* Wh = Wlin + 128 * 64;
    for (int i = t; i < 64 * 16; i += 256)
        ((float4*)wh)[i] = ((const float4*)Wh)[i];
    for (int i = t; i < 64 * 40; i += 256) {
        int k = i / 40, j = i % 40;
        wc[k * 80 + j]      = Wl2[i];
        wc[k * 80 + 40 + j] = Wr2[i];
    }
    __syncthreads();

    int m = t & 63, cg = t >> 6;
    int r = row0 + m;

    // --- phase A: h (64 cols)
    {
        unsigned long long acc[8] = {};
        const float* hrow = hd + m * 65;
#pragma unroll 4
        for (int k = 0; k < 64; k++) {
            unsigned long long a2 = pack2(hrow[k]);
            const ulonglong2* wp = (const ulonglong2*)(wh + k * 64 + cg * 16);
            ulonglong2 b0 = wp[0], b1 = wp[1];
            FMA2(acc[0], a2, b0.x); FMA2(acc[1], a2, b0.y);
            FMA2(acc[2], a2, b1.x); FMA2(acc[3], a2, b1.y);
            b0 = wp[2]; b1 = wp[3];
            FMA2(acc[4], a2, b0.x); FMA2(acc[5], a2, b0.y);
            FMA2(acc[6], a2, b1.x); FMA2(acc[7], a2, b1.y);
        }
        float* f = (float*)acc;
        float* hout = hs + m * 65 + cg * 16;
        if (r < N_NODES) {
            const float4* xwv = (const float4*)(g_cat + r * 192 + 128 + cg * 16);
            const float4* bb  = (const float4*)(blin + cg * 16);
#pragma unroll
            for (int q = 0; q < 4; q++) {
                float4 xv = xwv[q], bv = bb[q];
                hout[q * 4 + 0] = fmaxf(f[q * 4 + 0] + xv.x + bv.x, 0.f);
                hout[q * 4 + 1] = fmaxf(f[q * 4 + 1] + xv.y + bv.y, 0.f);
                hout[q * 4 + 2] = fmaxf(f[q * 4 + 2] + xv.z + bv.z, 0.f);
                hout[q * 4 + 3] = fmaxf(f[q * 4 + 3] + xv.w + bv.w, 0.f);
            }
        } else {
#pragma unroll
            for (int c = 0; c < 16; c++) hout[c] = 0.f;
        }
    }
    __syncthreads();

    // --- phase B: [z | hr] (80 cols)
    {
        unsigned long long acc[10] = {};
        const float* hrow = hs + m * 65;
#pragma unroll 4
        for (int k = 0; k < 64; k++) {
            unsigned long long a2 = pack2(hrow[k]);
            const ulonglong2* wp = (const ulonglong2*)(wc + k * 80 + cg * 20);
            ulonglong2 w0 = wp[0], w1 = wp[1];
            FMA2(acc[0], a2, w0.x); FMA2(acc[1], a2, w0.y);
            FMA2(acc[2], a2, w1.x); FMA2(acc[3], a2, w1.y);
            w0 = wp[2]; w1 = wp[3];
            FMA2(acc[4], a2, w0.x); FMA2(acc[5], a2, w0.y);
            FMA2(acc[6], a2, w1.x); FMA2(acc[7], a2, w1.y);
            w0 = wp[4];
            FMA2(acc[8], a2, w0.x); FMA2(acc[9], a2, w0.y);
        }
        if (r < N_NODES) {
            float* f = (float*)acc;
            float* dst = (cg < 2) ? (g_z + r * 40 + cg * 20)
                                  : (g_hr + r * 40 + (cg - 2) * 20);
            float4* d4 = (float4*)dst;
            d4[0] = make_float4(f[0],  f[1],  f[2],  f[3]);
            d4[1] = make_float4(f[4],  f[5],  f[6],  f[7]);
            d4[2] = make_float4(f[8],  f[9],  f[10], f[11]);
            d4[3] = make_float4(f[12], f[13], f[14], f[15]);
            d4[4] = make_float4(f[16], f[17], f[18], f[19]);
        }
    }
}

// ---------------- gather2 + node2 epilogue -------------------------------------
// 16 lanes per node (10 active for data); out = l2norm(sum/deg + bl2 + hr)
__global__ void k_gather2(const float* __restrict__ bl2, float* __restrict__ out) {
    int idx = blockIdx.x * 256 + threadIdx.x;   // exactly N*16 threads
    int node = idx >> 4, j = idx & 15;
    int beg = g_off[node], end = g_off[node + 1];
    const float4* z4 = (const float4*)g_z;

    float4 acc = make_float4(0.f, 0.f, 0.f, 0.f);
    for (int e = beg; e < end; e++) {
        int src = g_csr[e];
        if (j < 10) {
            float4 v = z4[src * 10 + j];
            acc.x += v.x; acc.y += v.y; acc.z += v.z; acc.w += v.w;
        }
    }
    float inv = 1.0f / fmaxf((float)(end - beg), 1.0f);
    float4 v = make_float4(0.f, 0.f, 0.f, 0.f);
    if (j < 10) {
        float4 b  = ((const float4*)bl2)[j];
        float4 hr = ((const float4*)g_hr)[node * 10 + j];
        v.x = acc.x * inv + b.x + hr.x;
        v.y = acc.y * inv + b.y + hr.y;
        v.z = acc.z * inv + b.z + hr.z;
        v.w = acc.w * inv + b.w + hr.w;
    }
    float ss = v.x * v.x + v.y * v.y + v.z * v.z + v.w * v.w;
    ss += __shfl_xor_sync(0xffffffffu, ss, 8);
    ss += __shfl_xor_sync(0xffffffffu, ss, 4);
    ss += __shfl_xor_sync(0xffffffffu, ss, 2);
    ss += __shfl_xor_sync(0xffffffffu, ss, 1);
    float sc = 1.0f / fmaxf(sqrtf(ss), 1e-12f);
    if (j < 10) {
        float4* op = (float4*)(out + node * 40 + j * 4);
        *op = make_float4(v.x * sc, v.y * sc, v.z * sc, v.w * sc);
    }
}

// ---------------- launch -----------------------------------------------------
extern "C" void kernel_launch(void* const* d_in, const int* in_sizes, int n_in,
                              void* d_out, int out_size) {
    const float* x    = (const float*)d_in[0];
    const int*   ei32 = (const int*)d_in[1];   // raw 32-bit view; layout probed on device
    const float* Wl1  = (const float*)d_in[2];
    const float* bl1  = (const float*)d_in[3];
    const float* Wr1  = (const float*)d_in[4];
    const float* Wlin = (const float*)d_in[5];
    const float* blin = (const float*)d_in[6];
    const float* Wl2  = (const float*)d_in[7];
    const float* bl2  = (const float*)d_in[8];
    const float* Wr2  = (const float*)d_in[9];
    float* out = (float*)d_out;

    const int SMEM1 = (64 * 129 + 128 * 192) * 4;                     // 131,328 B
    const int SMEM2 = (64 * 65 + 64 * 64 + 64 * 65 + 64 * 80) * 4;    // 70,144 B
    cudaFuncSetAttribute(k_gemm1, cudaFuncAttributeMaxDynamicSharedMemorySize, SMEM1);
    cudaFuncSetAttribute(k_gemm2, cudaFuncAttributeMaxDynamicSharedMemorySize, SMEM2);

    k_detect<<<1, 256>>>(ei32);
    k_zero<<<196, 256>>>();
    k_prep<<<3125, 256>>>(ei32);
    k_scan<<<1, 1024>>>();
    k_fill<<<3125, 256>>>();
    k_gemm1<<<782, 256, SMEM1>>>(x, Wl1, Wr1, Wlin);
    k_gather1<<<3125, 256>>>(bl1);           // N*16 / 256
    k_gemm2<<<782, 256, SMEM2>>>(Wlin, blin, Wl2, Wr2);
    k_gather2<<<3125, 256>>>(bl2, out);      // N*16 / 256
}

// round 6
// speedup vs baseline: 1.3874x; 1.3874x over previous
#include <cuda_runtime.h>

#define N_NODES 50000
#define N_EDGES 800000
#define F_IN    128
#define H_DIM   64
#define C_OUT   40

// ---------------- scratch (device globals) -----------------------------------
__device__ __align__(16) float g_cat[N_NODES * 192];       // [y1 | xr | xw] per node
__device__ __align__(16) float g_hidden[N_NODES * H_DIM];  // relu(l2norm(conv1))
__device__ __align__(16) float g_z[N_NODES * C_OUT];       // h @ Wl2
__device__ __align__(16) float g_hr[N_NODES * C_OUT];      // h @ Wr2
__device__ __align__(16) int2  g_srcdst[N_EDGES];          // repacked (src,dst)
__device__ __align__(16) int   g_deg[N_NODES];             // in-degree histogram
__device__ __align__(16) int   g_off[N_NODES + 1];         // CSR offsets
__device__ __align__(16) int   g_pos[N_NODES];             // fill cursors (init = off)
__device__ __align__(16) int   g_csr[N_EDGES];             // CSR src lists (by dst)
__device__ __align__(16) int   g_part[256];                // block partial sums
__device__ int g_is64;                                     // edge dtype flag

// ---------------- helpers ---------------------------------------------------
__device__ __forceinline__ unsigned long long pack2(float a) {
    unsigned long long r;
    asm("mov.b64 %0, {%1, %1};" : "=l"(r) : "f"(a));
    return r;
}
// packed fp32x2 FMA: 2 fp32 FMAs per instruction (sm_100+), exact fp32 numerics
#define FMA2(d, a, b) asm("fma.rn.f32x2 %0, %1, %2, %0;" : "+l"(d) : "l"(a), "l"(b))

// ---------------- init: zero histogram + dtype probe ---------------------------
// blocks 0..195 zero g_deg; block 196 probes edge dtype.
// int64 values < 50000 -> every odd 32-bit word is 0; int32 data -> not all zero.
__global__ void k_init(const int* __restrict__ ei32) {
    if (blockIdx.x < 196) {
        int i = blockIdx.x * 256 + threadIdx.x;
        if (i < N_NODES) g_deg[i] = 0;
        return;
    }
    __shared__ int s_any;
    if (threadIdx.x == 0) s_any = 0;
    __syncthreads();
    int any = 0;
    for (int s = threadIdx.x; s < 4096; s += 256) {
        int i = s * 195;
        if (ei32[2 * i + 1] != 0) any = 1;
    }
    if (any) atomicOr(&s_any, 1);
    __syncthreads();
    if (threadIdx.x == 0) g_is64 = (s_any == 0);
}

// ---------------- repack edges + histogram ------------------------------------
__global__ void k_prep(const int* __restrict__ ei32) {
    int e = blockIdx.x * 256 + threadIdx.x;
    if (e >= N_EDGES) return;
    int2 p;
    if (g_is64) {                        // int64 layout: low word at 2*idx
        p.x = ei32[2 * e];
        p.y = ei32[2 * (N_EDGES + e)];
    } else {                             // int32 layout
        p.x = ei32[e];
        p.y = ei32[N_EDGES + e];
    }
    g_srcdst[e] = p;
    atomicAdd(&g_deg[p.y], 1);
}

// ---------------- parallel scan phase A: per-block sums ------------------------
__global__ void k_scan_a() {
    __shared__ int s[256];
    int i = blockIdx.x * 256 + threadIdx.x;
    s[threadIdx.x] = (i < N_NODES) ? g_deg[i] : 0;
    __syncthreads();
#pragma unroll
    for (int o = 128; o > 0; o >>= 1) {
        if (threadIdx.x < o) s[threadIdx.x] += s[threadIdx.x + o];
        __syncthreads();
    }
    if (threadIdx.x == 0) g_part[blockIdx.x] = s[0];
}

// ---------------- phase B: exclusive scan of 196 partials (1 block) ------------
__global__ void k_scan_b() {
    __shared__ int s[256];
    int t = threadIdx.x;
    int v = (t < 196) ? g_part[t] : 0;
    s[t] = v;
    __syncthreads();
#pragma unroll
    for (int o = 1; o < 256; o <<= 1) {
        int u = (t >= o) ? s[t - o] : 0;
        __syncthreads();
        s[t] += u;
        __syncthreads();
    }
    g_part[t] = s[t] - v;                // exclusive
}

// ---------------- phase C: local scan + base -> offsets + cursors ---------------
__global__ void k_scan_c() {
    __shared__ int s[256];
    int t = threadIdx.x;
    int i = blockIdx.x * 256 + t;
    int v = (i < N_NODES) ? g_deg[i] : 0;
    s[t] = v;
    __syncthreads();
#pragma unroll
    for (int o = 1; o < 256; o <<= 1) {
        int u = (t >= o) ? s[t - o] : 0;
        __syncthreads();
        s[t] += u;
        __syncthreads();
    }
    int excl = g_part[blockIdx.x] + s[t] - v;
    if (i < N_NODES) {
        g_off[i] = excl;
        g_pos[i] = excl;
        if (i == N_NODES - 1) g_off[N_NODES] = excl + v;
    }
}

// ---------------- CSR fill ------------------------------------------------------
__global__ void k_fill() {
    int e = blockIdx.x * 256 + threadIdx.x;
    if (e >= N_EDGES) return;
    int2 sd = g_srcdst[e];
    int slot = atomicAdd(&g_pos[sd.y], 1);
    g_csr[slot] = sd.x;
}

// ---------------- GEMM1 fused: g_cat[r][0:192] = x[r] @ [Wl1|Wr1|Wlin_top] ------
// 64 rows x 192 cols per block; thread = 2 rows x 24 cols (f32x2 FMA).
// K split into 2 chunks of 64 -> smem 82KB -> 2 blocks/SM for latency hiding.
__global__ void __launch_bounds__(256, 2) k_gemm1(const float* __restrict__ x,
                        const float* __restrict__ Wl1,
                        const float* __restrict__ Wr1,
                        const float* __restrict__ Wlin) {
    extern __shared__ float sm[];
    float* xs = sm;               // [64][129]
    float* ws = sm + 64 * 129;    // [64][192]  (one K-chunk of weights)

    int row0 = blockIdx.x * 64;
    int t = threadIdx.x;

    // x tile: 64 rows x 32 float4 (all 128 k)
    for (int i = t; i < 64 * 32; i += 256) {
        int m = i >> 5, kc = i & 31;
        int r = row0 + m;
        float4 v = (r < N_NODES) ? ((const float4*)x)[r * 32 + kc]
                                 : make_float4(0.f, 0.f, 0.f, 0.f);
        float* d = xs + m * 129 + kc * 4;
        d[0] = v.x; d[1] = v.y; d[2] = v.z; d[3] = v.w;
    }

    const float4* wl1 = (const float4*)Wl1;
    const float4* wr1 = (const float4*)Wr1;
    const float4* wli = (const float4*)Wlin;

    int rp = t >> 3, cg = t & 7;           // row pair, column group (24 cols)
    const float* xr0 = xs + (2 * rp) * 129;
    const float* xr1 = xr0 + 129;
    unsigned long long acc[24] = {};       // [0..11] row0, [12..23] row1

    for (int kt = 0; kt < 2; kt++) {
        if (kt) __syncthreads();           // prior chunk's reads complete
        // weight chunk: rows kt*64 .. +64, 48 float4/row
        for (int i = t; i < 64 * 48; i += 256) {
            int k = i / 48, c = i % 48;
            int kk = kt * 64 + k;
            float4 v = (c < 16) ? wl1[kk * 16 + c]
                     : (c < 32) ? wr1[kk * 16 + (c - 16)]
                                : wli[kk * 16 + (c - 32)];
            ((float4*)(ws + k * 192))[c] = v;
        }
        __syncthreads();

        const float* x0 = xr0 + kt * 64;
        const float* x1 = xr1 + kt * 64;
#pragma unroll 2
        for (int k = 0; k < 64; k++) {
            unsigned long long a0 = pack2(x0[k]);
            unsigned long long a1 = pack2(x1[k]);
            const ulonglong2* wp = (const ulonglong2*)(ws + k * 192 + cg * 24);
            ulonglong2 w0 = wp[0], w1 = wp[1], w2 = wp[2];
            ulonglong2 w3 = wp[3], w4 = wp[4], w5 = wp[5];
            FMA2(acc[0],  a0, w0.x); FMA2(acc[1],  a0, w0.y);
            FMA2(acc[2],  a0, w1.x); FMA2(acc[3],  a0, w1.y);
            FMA2(acc[4],  a0, w2.x); FMA2(acc[5],  a0, w2.y);
            FMA2(acc[6],  a0, w3.x); FMA2(acc[7],  a0, w3.y);
            FMA2(acc[8],  a0, w4.x); FMA2(acc[9],  a0, w4.y);
            FMA2(acc[10], a0, w5.x); FMA2(acc[11], a0, w5.y);
            FMA2(acc[12], a1, w0.x); FMA2(acc[13], a1, w0.y);
            FMA2(acc[14], a1, w1.x); FMA2(acc[15], a1, w1.y);
            FMA2(acc[16], a1, w2.x); FMA2(acc[17], a1, w2.y);
            FMA2(acc[18], a1, w3.x); FMA2(acc[19], a1, w3.y);
            FMA2(acc[20], a1, w4.x); FMA2(acc[21], a1, w4.y);
            FMA2(acc[22], a1, w5.x); FMA2(acc[23], a1, w5.y);
        }
    }

    int r0 = row0 + 2 * rp, r1 = r0 + 1;
    float* f0 = (float*)acc;
    float* f1 = (float*)(acc + 12);
    if (r0 < N_NODES) {
        float4* o = (float4*)(g_cat + r0 * 192 + cg * 24);
#pragma unroll
        for (int q = 0; q < 6; q++)
            o[q] = make_float4(f0[4 * q], f0[4 * q + 1], f0[4 * q + 2], f0[4 * q + 3]);
    }
    if (r1 < N_NODES) {
        float4* o = (float4*)(g_cat + r1 * 192 + cg * 24);
#pragma unroll
        for (int q = 0; q < 6; q++)
            o[q] = make_float4(f1[4 * q], f1[4 * q + 1], f1[4 * q + 2], f1[4 * q + 3]);
    }
}

// ---------------- gather1 + node1 epilogue -------------------------------------
// 16 lanes per node; gather y1 rows (g_cat cols 0-63) over CSR, then
// hidden = relu(l2norm(sum/deg + bl1 + xr))
__global__ void k_gather1(const float* __restrict__ bl1) {
    int idx = blockIdx.x * 256 + threadIdx.x;   // exactly N*16 threads
    int node = idx >> 4, j = idx & 15;
    int beg = g_off[node], end = g_off[node + 1];
    const float4* cat4 = (const float4*)g_cat;

    float4 acc = make_float4(0.f, 0.f, 0.f, 0.f);
    for (int e = beg; e < end; e++) {
        int src = g_csr[e];                      // broadcast within 16-lane group
        float4 v = cat4[src * 48 + j];
        acc.x += v.x; acc.y += v.y; acc.z += v.z; acc.w += v.w;
    }
    float inv = 1.0f / fmaxf((float)(end - beg), 1.0f);
    float4 b  = ((const float4*)bl1)[j];
    float4 xr = cat4[node * 48 + 16 + j];
    float4 v;
    v.x = acc.x * inv + b.x + xr.x;
    v.y = acc.y * inv + b.y + xr.y;
    v.z = acc.z * inv + b.z + xr.z;
    v.w = acc.w * inv + b.w + xr.w;
    float ss = v.x * v.x + v.y * v.y + v.z * v.z + v.w * v.w;
    ss += __shfl_xor_sync(0xffffffffu, ss, 8);
    ss += __shfl_xor_sync(0xffffffffu, ss, 4);
    ss += __shfl_xor_sync(0xffffffffu, ss, 2);
    ss += __shfl_xor_sync(0xffffffffu, ss, 1);
    float sc = 1.0f / fmaxf(sqrtf(ss), 1e-12f);
    float4 h;
    h.x = fmaxf(v.x * sc, 0.f);
    h.y = fmaxf(v.y * sc, 0.f);
    h.z = fmaxf(v.z * sc, 0.f);
    h.w = fmaxf(v.w * sc, 0.f);
    ((float4*)g_hidden)[node * 16 + j] = h;
}

// ---------------- GEMM2 (fused): h = relu(xw + hidden@Wh + blin);
//                  z = h@Wl2 ; hr = h@Wr2
__global__ void k_gemm2(const float* __restrict__ Wlin,
                        const float* __restrict__ blin,
                        const float* __restrict__ Wl2,
                        const float* __restrict__ Wr2) {
    extern __shared__ float sm[];
    float* hd = sm;                 // [64][65]
    float* wh = hd + 64 * 65;       // [64][64]
    float* hs = wh + 64 * 64;       // [64][65]
    float* wc = hs + 64 * 65;       // [64][80]

    int row0 = blockIdx.x * 64;
    int t = threadIdx.x;

    for (int i = t; i < 64 * 16; i += 256) {
        int m = i >> 4, kc = i & 15;
        int r = row0 + m;
        float4 v = (r < N_NODES) ? ((const float4*)g_hidden)[r * 16 + kc]
                                 : make_float4(0.f, 0.f, 0.f, 0.f);
        float* d = hd + m * 65 + kc * 4;
        d[0] = v.x; d[1] = v.y; d[2] = v.z; d[3] = v.w;
    }
    const float* Wh = Wlin + 128 * 64;
    for (int i = t; i < 64 * 16; i += 256)
        ((float4*)wh)[i] = ((const float4*)Wh)[i];
    for (int i = t; i < 64 * 40; i += 256) {
        int k = i / 40, j = i % 40;
        wc[k * 80 + j]      = Wl2[i];
        wc[k * 80 + 40 + j] = Wr2[i];
    }
    __syncthreads();

    int m = t & 63, cg = t >> 6;
    int r = row0 + m;

    // --- phase A: h (64 cols)
    {
        unsigned long long acc[8] = {};
        const float* hrow = hd + m * 65;
#pragma unroll 4
        for (int k = 0; k < 64; k++) {
            unsigned long long a2 = pack2(hrow[k]);
            const ulonglong2* wp = (const ulonglong2*)(wh + k * 64 + cg * 16);
            ulonglong2 b0 = wp[0], b1 = wp[1];
            FMA2(acc[0], a2, b0.x); FMA2(acc[1], a2, b0.y);
            FMA2(acc[2], a2, b1.x); FMA2(acc[3], a2, b1.y);
            b0 = wp[2]; b1 = wp[3];
            FMA2(acc[4], a2, b0.x); FMA2(acc[5], a2, b0.y);
            FMA2(acc[6], a2, b1.x); FMA2(acc[7], a2, b1.y);
        }
        float* f = (float*)acc;
        float* hout = hs + m * 65 + cg * 16;
        if (r < N_NODES) {
            const float4* xwv = (const float4*)(g_cat + r * 192 + 128 + cg * 16);
            const float4* bb  = (const float4*)(blin + cg * 16);
#pragma unroll
            for (int q = 0; q < 4; q++) {
                float4 xv = xwv[q], bv = bb[q];
                hout[q * 4 + 0] = fmaxf(f[q * 4 + 0] + xv.x + bv.x, 0.f);
                hout[q * 4 + 1] = fmaxf(f[q * 4 + 1] + xv.y + bv.y, 0.f);
                hout[q * 4 + 2] = fmaxf(f[q * 4 + 2] + xv.z + bv.z, 0.f);
                hout[q * 4 + 3] = fmaxf(f[q * 4 + 3] + xv.w + bv.w, 0.f);
            }
        } else {
#pragma unroll
            for (int c = 0; c < 16; c++) hout[c] = 0.f;
        }
    }
    __syncthreads();

    // --- phase B: [z | hr] (80 cols)
    {
        unsigned long long acc[10] = {};
        const float* hrow = hs + m * 65;
#pragma unroll 4
        for (int k = 0; k < 64; k++) {
            unsigned long long a2 = pack2(hrow[k]);
            const ulonglong2* wp = (const ulonglong2*)(wc + k * 80 + cg * 20);
            ulonglong2 w0 = wp[0], w1 = wp[1];
            FMA2(acc[0], a2, w0.x); FMA2(acc[1], a2, w0.y);
            FMA2(acc[2], a2, w1.x); FMA2(acc[3], a2, w1.y);
            w0 = wp[2]; w1 = wp[3];
            FMA2(acc[4], a2, w0.x); FMA2(acc[5], a2, w0.y);
            FMA2(acc[6], a2, w1.x); FMA2(acc[7], a2, w1.y);
            w0 = wp[4];
            FMA2(acc[8], a2, w0.x); FMA2(acc[9], a2, w0.y);
        }
        if (r < N_NODES) {
            float* f = (float*)acc;
            float* dst = (cg < 2) ? (g_z + r * 40 + cg * 20)
                                  : (g_hr + r * 40 + (cg - 2) * 20);
            float4* d4 = (float4*)dst;
            d4[0] = make_float4(f[0],  f[1],  f[2],  f[3]);
            d4[1] = make_float4(f[4],  f[5],  f[6],  f[7]);
            d4[2] = make_float4(f[8],  f[9],  f[10], f[11]);
            d4[3] = make_float4(f[12], f[13], f[14], f[15]);
            d4[4] = make_float4(f[16], f[17], f[18], f[19]);
        }
    }
}

// ---------------- gather2 + node2 epilogue -------------------------------------
__global__ void k_gather2(const float* __restrict__ bl2, float* __restrict__ out) {
    int idx = blockIdx.x * 256 + threadIdx.x;   // exactly N*16 threads
    int node = idx >> 4, j = idx & 15;
    int beg = g_off[node], end = g_off[node + 1];
    const float4* z4 = (const float4*)g_z;

    float4 acc = make_float4(0.f, 0.f, 0.f, 0.f);
    for (int e = beg; e < end; e++) {
        int src = g_csr[e];
        if (j < 10) {
            float4 v = z4[src * 10 + j];
            acc.x += v.x; acc.y += v.y; acc.z += v.z; acc.w += v.w;
        }
    }
    float inv = 1.0f / fmaxf((float)(end - beg), 1.0f);
    float4 v = make_float4(0.f, 0.f, 0.f, 0.f);
    if (j < 10) {
        float4 b  = ((const float4*)bl2)[j];
        float4 hr = ((const float4*)g_hr)[node * 10 + j];
        v.x = acc.x * inv + b.x + hr.x;
        v.y = acc.y * inv + b.y + hr.y;
        v.z = acc.z * inv + b.z + hr.z;
        v.w = acc.w * inv + b.w + hr.w;
    }
    float ss = v.x * v.x + v.y * v.y + v.z * v.z + v.w * v.w;
    ss += __shfl_xor_sync(0xffffffffu, ss, 8);
    ss += __shfl_xor_sync(0xffffffffu, ss, 4);
    ss += __shfl_xor_sync(0xffffffffu, ss, 2);
    ss += __shfl_xor_sync(0xffffffffu, ss, 1);
    float sc = 1.0f / fmaxf(sqrtf(ss), 1e-12f);
    if (j < 10) {
        float4* op = (float4*)(out + node * 40 + j * 4);
        *op = make_float4(v.x * sc, v.y * sc, v.z * sc, v.w * sc);
    }
}

// ---------------- launch -----------------------------------------------------
extern "C" void kernel_launch(void* const* d_in, const int* in_sizes, int n_in,
                              void* d_out, int out_size) {
    const float* x    = (const float*)d_in[0];
    const int*   ei32 = (const int*)d_in[1];   // raw 32-bit view; layout probed on device
    const float* Wl1  = (const float*)d_in[2];
    const float* bl1  = (const float*)d_in[3];
    const float* Wr1  = (const float*)d_in[4];
    const float* Wlin = (const float*)d_in[5];
    const float* blin = (const float*)d_in[6];
    const float* Wl2  = (const float*)d_in[7];
    const float* bl2  = (const float*)d_in[8];
    const float* Wr2  = (const float*)d_in[9];
    float* out = (float*)d_out;

    const int SMEM1 = (64 * 129 + 64 * 192) * 4;                      // 82,176 B
    const int SMEM2 = (64 * 65 + 64 * 64 + 64 * 65 + 64 * 80) * 4;    // 70,144 B
    cudaFuncSetAttribute(k_gemm1, cudaFuncAttributeMaxDynamicSharedMemorySize, SMEM1);
    cudaFuncSetAttribute(k_gemm2, cudaFuncAttributeMaxDynamicSharedMemorySize, SMEM2);

    k_init<<<197, 256>>>(ei32);
    k_prep<<<3125, 256>>>(ei32);
    k_scan_a<<<196, 256>>>();
    k_scan_b<<<1, 256>>>();
    k_scan_c<<<196, 256>>>();
    k_fill<<<3125, 256>>>();
    k_gemm1<<<782, 256, SMEM1>>>(x, Wl1, Wr1, Wlin);
    k_gather1<<<3125, 256>>>(bl1);           // N*16 / 256
    k_gemm2<<<782, 256, SMEM2>>>(Wlin, blin, Wl2, Wr2);
    k_gather2<<<3125, 256>>>(bl2, out);      // N*16 / 256
}

// round 7
// speedup vs baseline: 1.4977x; 1.0796x over previous
#include <cuda_runtime.h>

#define N_NODES 50000
#define N_EDGES 800000
#define F_IN    128
#define H_DIM   64
#define C_OUT   40

// ---------------- scratch (device globals) -----------------------------------
__device__ __align__(16) float g_cat[N_NODES * 192];       // [y1 | xr | xw] per node
__device__ __align__(16) float g_hidden[N_NODES * H_DIM];  // relu(l2norm(conv1))
__device__ __align__(16) float g_z[N_NODES * C_OUT];       // h @ Wl2
__device__ __align__(16) float g_hr[N_NODES * C_OUT];      // h @ Wr2
__device__ __align__(16) int2  g_srcdst[N_EDGES];          // repacked (src,dst)
__device__ __align__(16) int   g_deg[N_NODES];             // in-degree histogram
__device__ __align__(16) int   g_off[N_NODES + 1];         // CSR offsets
__device__ __align__(16) int   g_pos[N_NODES];             // fill cursors (init = off)
__device__ __align__(16) int   g_csr[N_EDGES];             // CSR src lists (by dst)
__device__ __align__(16) int   g_part[256];                // block partial sums
__device__ int g_is64;                                     // edge dtype flag

// ---------------- helpers ---------------------------------------------------
__device__ __forceinline__ unsigned long long pack2(float a) {
    unsigned long long r;
    asm("mov.b64 %0, {%1, %1};" : "=l"(r) : "f"(a));
    return r;
}
// packed fp32x2 FMA: 2 fp32 FMAs per instruction (sm_100+), exact fp32 numerics
#define FMA2(d, a, b) asm("fma.rn.f32x2 %0, %1, %2, %0;" : "+l"(d) : "l"(a), "l"(b))

__device__ __forceinline__ void acc_add(float4& a, float4 v) {
    a.x += v.x; a.y += v.y; a.z += v.z; a.w += v.w;
}

// ---------------- init: zero histogram + dtype probe ---------------------------
__global__ void k_init(const int* __restrict__ ei32) {
    if (blockIdx.x < 196) {
        int i = blockIdx.x * 256 + threadIdx.x;
        if (i < N_NODES) g_deg[i] = 0;
        return;
    }
    __shared__ int s_any;
    if (threadIdx.x == 0) s_any = 0;
    __syncthreads();
    int any = 0;
    for (int s = threadIdx.x; s < 4096; s += 256) {
        int i = s * 195;
        if (ei32[2 * i + 1] != 0) any = 1;
    }
    if (any) atomicOr(&s_any, 1);
    __syncthreads();
    if (threadIdx.x == 0) g_is64 = (s_any == 0);
}

// ---------------- repack edges + histogram ------------------------------------
__global__ void k_prep(const int* __restrict__ ei32) {
    int e = blockIdx.x * 256 + threadIdx.x;
    if (e >= N_EDGES) return;
    int2 p;
    if (g_is64) {                        // int64 layout: low word at 2*idx
        p.x = ei32[2 * e];
        p.y = ei32[2 * (N_EDGES + e)];
    } else {                             // int32 layout
        p.x = ei32[e];
        p.y = ei32[N_EDGES + e];
    }
    g_srcdst[e] = p;
    atomicAdd(&g_deg[p.y], 1);
}

// ---------------- parallel scan phase A: per-block sums ------------------------
__global__ void k_scan_a() {
    __shared__ int s[256];
    int i = blockIdx.x * 256 + threadIdx.x;
    s[threadIdx.x] = (i < N_NODES) ? g_deg[i] : 0;
    __syncthreads();
#pragma unroll
    for (int o = 128; o > 0; o >>= 1) {
        if (threadIdx.x < o) s[threadIdx.x] += s[threadIdx.x + o];
        __syncthreads();
    }
    if (threadIdx.x == 0) g_part[blockIdx.x] = s[0];
}

// ---------------- phase B: exclusive scan of 196 partials (1 block) ------------
__global__ void k_scan_b() {
    __shared__ int s[256];
    int t = threadIdx.x;
    int v = (t < 196) ? g_part[t] : 0;
    s[t] = v;
    __syncthreads();
#pragma unroll
    for (int o = 1; o < 256; o <<= 1) {
        int u = (t >= o) ? s[t - o] : 0;
        __syncthreads();
        s[t] += u;
        __syncthreads();
    }
    g_part[t] = s[t] - v;                // exclusive
}

// ---------------- phase C: local scan + base -> offsets + cursors ---------------
__global__ void k_scan_c() {
    __shared__ int s[256];
    int t = threadIdx.x;
    int i = blockIdx.x * 256 + t;
    int v = (i < N_NODES) ? g_deg[i] : 0;
    s[t] = v;
    __syncthreads();
#pragma unroll
    for (int o = 1; o < 256; o <<= 1) {
        int u = (t >= o) ? s[t - o] : 0;
        __syncthreads();
        s[t] += u;
        __syncthreads();
    }
    int excl = g_part[blockIdx.x] + s[t] - v;
    if (i < N_NODES) {
        g_off[i] = excl;
        g_pos[i] = excl;
        if (i == N_NODES - 1) g_off[N_NODES] = excl + v;
    }
}

// ---------------- CSR fill ------------------------------------------------------
__global__ void k_fill() {
    int e = blockIdx.x * 256 + threadIdx.x;
    if (e >= N_EDGES) return;
    int2 sd = g_srcdst[e];
    int slot = atomicAdd(&g_pos[sd.y], 1);
    g_csr[slot] = sd.x;
}

// ---------------- GEMM1 fused: g_cat[r][0:192] = x[r] @ [Wl1|Wr1|Wlin_top] ------
// 64 rows x 192 cols per block; thread = 2 rows x 24 cols (f32x2 FMA).
// K split into 2 chunks of 64 -> smem 82KB -> 2 blocks/SM.
__global__ void __launch_bounds__(256, 2) k_gemm1(const float* __restrict__ x,
                        const float* __restrict__ Wl1,
                        const float* __restrict__ Wr1,
                        const float* __restrict__ Wlin) {
    extern __shared__ float sm[];
    float* xs = sm;               // [64][129]
    float* ws = sm + 64 * 129;    // [64][192]  (one K-chunk of weights)

    int row0 = blockIdx.x * 64;
    int t = threadIdx.x;

    for (int i = t; i < 64 * 32; i += 256) {
        int m = i >> 5, kc = i & 31;
        int r = row0 + m;
        float4 v = (r < N_NODES) ? ((const float4*)x)[r * 32 + kc]
                                 : make_float4(0.f, 0.f, 0.f, 0.f);
        float* d = xs + m * 129 + kc * 4;
        d[0] = v.x; d[1] = v.y; d[2] = v.z; d[3] = v.w;
    }

    const float4* wl1 = (const float4*)Wl1;
    const float4* wr1 = (const float4*)Wr1;
    const float4* wli = (const float4*)Wlin;

    int rp = t >> 3, cg = t & 7;
    const float* xr0 = xs + (2 * rp) * 129;
    const float* xr1 = xr0 + 129;
    unsigned long long acc[24] = {};

    for (int kt = 0; kt < 2; kt++) {
        if (kt) __syncthreads();
        for (int i = t; i < 64 * 48; i += 256) {
            int k = i / 48, c = i % 48;
            int kk = kt * 64 + k;
            float4 v = (c < 16) ? wl1[kk * 16 + c]
                     : (c < 32) ? wr1[kk * 16 + (c - 16)]
                                : wli[kk * 16 + (c - 32)];
            ((float4*)(ws + k * 192))[c] = v;
        }
        __syncthreads();

        const float* x0 = xr0 + kt * 64;
        const float* x1 = xr1 + kt * 64;
#pragma unroll 2
        for (int k = 0; k < 64; k++) {
            unsigned long long a0 = pack2(x0[k]);
            unsigned long long a1 = pack2(x1[k]);
            const ulonglong2* wp = (const ulonglong2*)(ws + k * 192 + cg * 24);
            ulonglong2 w0 = wp[0], w1 = wp[1], w2 = wp[2];
            ulonglong2 w3 = wp[3], w4 = wp[4], w5 = wp[5];
            FMA2(acc[0],  a0, w0.x); FMA2(acc[1],  a0, w0.y);
            FMA2(acc[2],  a0, w1.x); FMA2(acc[3],  a0, w1.y);
            FMA2(acc[4],  a0, w2.x); FMA2(acc[5],  a0, w2.y);
            FMA2(acc[6],  a0, w3.x); FMA2(acc[7],  a0, w3.y);
            FMA2(acc[8],  a0, w4.x); FMA2(acc[9],  a0, w4.y);
            FMA2(acc[10], a0, w5.x); FMA2(acc[11], a0, w5.y);
            FMA2(acc[12], a1, w0.x); FMA2(acc[13], a1, w0.y);
            FMA2(acc[14], a1, w1.x); FMA2(acc[15], a1, w1.y);
            FMA2(acc[16], a1, w2.x); FMA2(acc[17], a1, w2.y);
            FMA2(acc[18], a1, w3.x); FMA2(acc[19], a1, w3.y);
            FMA2(acc[20], a1, w4.x); FMA2(acc[21], a1, w4.y);
            FMA2(acc[22], a1, w5.x); FMA2(acc[23], a1, w5.y);
        }
    }

    int r0 = row0 + 2 * rp, r1 = r0 + 1;
    float* f0 = (float*)acc;
    float* f1 = (float*)(acc + 12);
    if (r0 < N_NODES) {
        float4* o = (float4*)(g_cat + r0 * 192 + cg * 24);
#pragma unroll
        for (int q = 0; q < 6; q++)
            o[q] = make_float4(f0[4 * q], f0[4 * q + 1], f0[4 * q + 2], f0[4 * q + 3]);
    }
    if (r1 < N_NODES) {
        float4* o = (float4*)(g_cat + r1 * 192 + cg * 24);
#pragma unroll
        for (int q = 0; q < 6; q++)
            o[q] = make_float4(f1[4 * q], f1[4 * q + 1], f1[4 * q + 2], f1[4 * q + 3]);
    }
}

// ---------------- gather1 + node1 epilogue -------------------------------------
// 16 lanes per node; 4x-unrolled CSR gather (MLP=4), __ldg path.
__global__ void k_gather1(const float* __restrict__ bl1) {
    int idx = blockIdx.x * 256 + threadIdx.x;   // exactly N*16 threads
    int node = idx >> 4, j = idx & 15;
    int beg = g_off[node], end = g_off[node + 1];
    const float4* cat4 = (const float4*)g_cat;

    float4 acc = make_float4(0.f, 0.f, 0.f, 0.f);
    int e = beg;
    for (; e + 4 <= end; e += 4) {
        int s0 = g_csr[e], s1 = g_csr[e + 1], s2 = g_csr[e + 2], s3 = g_csr[e + 3];
        float4 v0 = __ldg(cat4 + s0 * 48 + j);
        float4 v1 = __ldg(cat4 + s1 * 48 + j);
        float4 v2 = __ldg(cat4 + s2 * 48 + j);
        float4 v3 = __ldg(cat4 + s3 * 48 + j);
        acc_add(acc, v0); acc_add(acc, v1); acc_add(acc, v2); acc_add(acc, v3);
    }
    for (; e < end; e++) {
        int src = g_csr[e];
        acc_add(acc, __ldg(cat4 + src * 48 + j));
    }

    float inv = 1.0f / fmaxf((float)(end - beg), 1.0f);
    float4 b  = ((const float4*)bl1)[j];
    float4 xr = cat4[node * 48 + 16 + j];
    float4 v;
    v.x = acc.x * inv + b.x + xr.x;
    v.y = acc.y * inv + b.y + xr.y;
    v.z = acc.z * inv + b.z + xr.z;
    v.w = acc.w * inv + b.w + xr.w;
    float ss = v.x * v.x + v.y * v.y + v.z * v.z + v.w * v.w;
    ss += __shfl_xor_sync(0xffffffffu, ss, 8);
    ss += __shfl_xor_sync(0xffffffffu, ss, 4);
    ss += __shfl_xor_sync(0xffffffffu, ss, 2);
    ss += __shfl_xor_sync(0xffffffffu, ss, 1);
    float sc = 1.0f / fmaxf(sqrtf(ss), 1e-12f);
    float4 h;
    h.x = fmaxf(v.x * sc, 0.f);
    h.y = fmaxf(v.y * sc, 0.f);
    h.z = fmaxf(v.z * sc, 0.f);
    h.w = fmaxf(v.w * sc, 0.f);
    ((float4*)g_hidden)[node * 16 + j] = h;
}

// ---------------- GEMM2 (fused): h = relu(xw + hidden@Wh + blin);
//                  z = h@Wl2 ; hr = h@Wr2
__global__ void k_gemm2(const float* __restrict__ Wlin,
                        const float* __restrict__ blin,
                        const float* __restrict__ Wl2,
                        const float* __restrict__ Wr2) {
    extern __shared__ float sm[];
    float* hd = sm;                 // [64][65]
    float* wh = hd + 64 * 65;       // [64][64]
    float* hs = wh + 64 * 64;       // [64][65]
    float* wc = hs + 64 * 65;       // [64][80]

    int row0 = blockIdx.x * 64;
    int t = threadIdx.x;

    for (int i = t; i < 64 * 16; i += 256) {
        int m = i >> 4, kc = i & 15;
        int r = row0 + m;
        float4 v = (r < N_NODES) ? ((const float4*)g_hidden)[r * 16 + kc]
                                 : make_float4(0.f, 0.f, 0.f, 0.f);
        float* d = hd + m * 65 + kc * 4;
        d[0] = v.x; d[1] = v.y; d[2] = v.z; d[3] = v.w;
    }
    const float* Wh = Wlin + 128 * 64;
    for (int i = t; i < 64 * 16; i += 256)
        ((float4*)wh)[i] = ((const float4*)Wh)[i];
    for (int i = t; i < 64 * 40; i += 256) {
        int k = i / 40, j = i % 40;
        wc[k * 80 + j]      = Wl2[i];
        wc[k * 80 + 40 + j] = Wr2[i];
    }
    __syncthreads();

    int m = t & 63, cg = t >> 6;
    int r = row0 + m;

    // --- phase A: h (64 cols)
    {
        unsigned long long acc[8] = {};
        const float* hrow = hd + m * 65;
#pragma unroll 4
        for (int k = 0; k < 64; k++) {
            unsigned long long a2 = pack2(hrow[k]);
            const ulonglong2* wp = (const ulonglong2*)(wh + k * 64 + cg * 16);
            ulonglong2 b0 = wp[0], b1 = wp[1];
            FMA2(acc[0], a2, b0.x); FMA2(acc[1], a2, b0.y);
            FMA2(acc[2], a2, b1.x); FMA2(acc[3], a2, b1.y);
            b0 = wp[2]; b1 = wp[3];
            FMA2(acc[4], a2, b0.x); FMA2(acc[5], a2, b0.y);
            FMA2(acc[6], a2, b1.x); FMA2(acc[7], a2, b1.y);
        }
        float* f = (float*)acc;
        float* hout = hs + m * 65 + cg * 16;
        if (r < N_NODES) {
            const float4* xwv = (const float4*)(g_cat + r * 192 + 128 + cg * 16);
            const float4* bb  = (const float4*)(blin + cg * 16);
#pragma unroll
            for (int q = 0; q < 4; q++) {
                float4 xv = xwv[q], bv = bb[q];
                hout[q * 4 + 0] = fmaxf(f[q * 4 + 0] + xv.x + bv.x, 0.f);
                hout[q * 4 + 1] = fmaxf(f[q * 4 + 1] + xv.y + bv.y, 0.f);
                hout[q * 4 + 2] = fmaxf(f[q * 4 + 2] + xv.z + bv.z, 0.f);
                hout[q * 4 + 3] = fmaxf(f[q * 4 + 3] + xv.w + bv.w, 0.f);
            }
        } else {
#pragma unroll
            for (int c = 0; c < 16; c++) hout[c] = 0.f;
        }
    }
    __syncthreads();

    // --- phase B: [z | hr] (80 cols)
    {
        unsigned long long acc[10] = {};
        const float* hrow = hs + m * 65;
#pragma unroll 4
        for (int k = 0; k < 64; k++) {
            unsigned long long a2 = pack2(hrow[k]);
            const ulonglong2* wp = (const ulonglong2*)(wc + k * 80 + cg * 20);
            ulonglong2 w0 = wp[0], w1 = wp[1];
            FMA2(acc[0], a2, w0.x); FMA2(acc[1], a2, w0.y);
            FMA2(acc[2], a2, w1.x); FMA2(acc[3], a2, w1.y);
            w0 = wp[2]; w1 = wp[3];
            FMA2(acc[4], a2, w0.x); FMA2(acc[5], a2, w0.y);
            FMA2(acc[6], a2, w1.x); FMA2(acc[7], a2, w1.y);
            w0 = wp[4];
            FMA2(acc[8], a2, w0.x); FMA2(acc[9], a2, w0.y);
        }
        if (r < N_NODES) {
            float* f = (float*)acc;
            float* dst = (cg < 2) ? (g_z + r * 40 + cg * 20)
                                  : (g_hr + r * 40 + (cg - 2) * 20);
            float4* d4 = (float4*)dst;
            d4[0] = make_float4(f[0],  f[1],  f[2],  f[3]);
            d4[1] = make_float4(f[4],  f[5],  f[6],  f[7]);
            d4[2] = make_float4(f[8],  f[9],  f[10], f[11]);
            d4[3] = make_float4(f[12], f[13], f[14], f[15]);
            d4[4] = make_float4(f[16], f[17], f[18], f[19]);
        }
    }
}

// ---------------- gather2 + node2 epilogue -------------------------------------
__global__ void k_gather2(const float* __restrict__ bl2, float* __restrict__ out) {
    int idx = blockIdx.x * 256 + threadIdx.x;   // exactly N*16 threads
    int node = idx >> 4, j = idx & 15;
    int beg = g_off[node], end = g_off[node + 1];
    const float4* z4 = (const float4*)g_z;

    float4 acc = make_float4(0.f, 0.f, 0.f, 0.f);
    if (j < 10) {
        int e = beg;
        for (; e + 4 <= end; e += 4) {
            int s0 = g_csr[e], s1 = g_csr[e + 1], s2 = g_csr[e + 2], s3 = g_csr[e + 3];
            float4 v0 = __ldg(z4 + s0 * 10 + j);
            float4 v1 = __ldg(z4 + s1 * 10 + j);
            float4 v2 = __ldg(z4 + s2 * 10 + j);
            float4 v3 = __ldg(z4 + s3 * 10 + j);
            acc_add(acc, v0); acc_add(acc, v1); acc_add(acc, v2); acc_add(acc, v3);
        }
        for (; e < end; e++) {
            int src = g_csr[e];
            acc_add(acc, __ldg(z4 + src * 10 + j));
        }
    }
    float inv = 1.0f / fmaxf((float)(end - beg), 1.0f);
    float4 v = make_float4(0.f, 0.f, 0.f, 0.f);
    if (j < 10) {
        float4 b  = ((const float4*)bl2)[j];
        float4 hr = ((const float4*)g_hr)[node * 10 + j];
        v.x = acc.x * inv + b.x + hr.x;
        v.y = acc.y * inv + b.y + hr.y;
        v.z = acc.z * inv + b.z + hr.z;
        v.w = acc.w * inv + b.w + hr.w;
    }
    float ss = v.x * v.x + v.y * v.y + v.z * v.z + v.w * v.w;
    ss += __shfl_xor_sync(0xffffffffu, ss, 8);
    ss += __shfl_xor_sync(0xffffffffu, ss, 4);
    ss += __shfl_xor_sync(0xffffffffu, ss, 2);
    ss += __shfl_xor_sync(0xffffffffu, ss, 1);
    float sc = 1.0f / fmaxf(sqrtf(ss), 1e-12f);
    if (j < 10) {
        float4* op = (float4*)(out + node * 40 + j * 4);
        *op = make_float4(v.x * sc, v.y * sc, v.z * sc, v.w * sc);
    }
}

// ---------------- launch -----------------------------------------------------
static cudaStream_t g_s2 = 0;
static cudaEvent_t  g_evA = 0, g_evB = 0;

extern "C" void kernel_launch(void* const* d_in, const int* in_sizes, int n_in,
                              void* d_out, int out_size) {
    const float* x    = (const float*)d_in[0];
    const int*   ei32 = (const int*)d_in[1];   // raw 32-bit view; layout probed on device
    const float* Wl1  = (const float*)d_in[2];
    const float* bl1  = (const float*)d_in[3];
    const float* Wr1  = (const float*)d_in[4];
    const float* Wlin = (const float*)d_in[5];
    const float* blin = (const float*)d_in[6];
    const float* Wl2  = (const float*)d_in[7];
    const float* bl2  = (const float*)d_in[8];
    const float* Wr2  = (const float*)d_in[9];
    float* out = (float*)d_out;

    if (!g_s2) {   // one-time resource creation (no device memory involved)
        cudaStreamCreateWithFlags(&g_s2, cudaStreamNonBlocking);
        cudaEventCreateWithFlags(&g_evA, cudaEventDisableTiming);
        cudaEventCreateWithFlags(&g_evB, cudaEventDisableTiming);
    }

    const int SMEM1 = (64 * 129 + 64 * 192) * 4;                      // 82,176 B
    const int SMEM2 = (64 * 65 + 64 * 64 + 64 * 65 + 64 * 80) * 4;    // 70,144 B
    cudaFuncSetAttribute(k_gemm1, cudaFuncAttributeMaxDynamicSharedMemorySize, SMEM1);
    cudaFuncSetAttribute(k_gemm2, cudaFuncAttributeMaxDynamicSharedMemorySize, SMEM2);

    // fork: CSR build chain on g_s2, concurrent with gemm1 on the main stream
    k_init<<<197, 256>>>(ei32);
    cudaEventRecord(g_evA, 0);
    cudaStreamWaitEvent(g_s2, g_evA, 0);

    k_prep<<<3125, 256, 0, g_s2>>>(ei32);
    k_scan_a<<<196, 256, 0, g_s2>>>();
    k_scan_b<<<1, 256, 0, g_s2>>>();
    k_scan_c<<<196, 256, 0, g_s2>>>();
    k_fill<<<3125, 256, 0, g_s2>>>();
    cudaEventRecord(g_evB, g_s2);

    k_gemm1<<<782, 256, SMEM1>>>(x, Wl1, Wr1, Wlin);   // main stream, overlapped

    cudaStreamWaitEvent(0, g_evB, 0);                  // join
    k_gather1<<<3125, 256>>>(bl1);
    k_gemm2<<<782, 256, SMEM2>>>(Wlin, blin, Wl2, Wr2);
    k_gather2<<<3125, 256>>>(bl2, out);
}

// round 8
// speedup vs baseline: 2.1068x; 1.4066x over previous
#include <cuda_runtime.h>

#define N_NODES 50000
#define N_EDGES 800000
#define F_IN    128
#define H_DIM   64
#define C_OUT   40

// ---------------- scratch (device globals) -----------------------------------
__device__ __align__(16) float g_cat[N_NODES * 192];       // [y1 | xr | xw] per node
__device__ __align__(16) float g_hidden[N_NODES * H_DIM];  // relu(l2norm(conv1))
__device__ __align__(16) float g_z[N_NODES * C_OUT];       // h @ Wl2
__device__ __align__(16) float g_hr[N_NODES * C_OUT];      // h @ Wr2
__device__ __align__(16) int2  g_srcdst[N_EDGES];          // repacked (src,dst)
__device__ __align__(16) int   g_deg[N_NODES];             // in-degree histogram
__device__ __align__(16) int   g_off[N_NODES + 1];         // CSR offsets
__device__ __align__(16) int   g_pos[N_NODES];             // fill cursors (init = off)
__device__ __align__(16) int   g_csr[N_EDGES];             // CSR src lists (by dst)
__device__ __align__(16) int   g_part[256];                // block partial sums
__device__ int g_is64;                                     // edge dtype flag

// ---------------- helpers ---------------------------------------------------
__device__ __forceinline__ unsigned long long pack2(float a) {
    unsigned long long r;
    asm("mov.b64 %0, {%1, %1};" : "=l"(r) : "f"(a));
    return r;
}
// packed fp32x2 FMA: 2 fp32 FMAs per instruction (sm_100+), exact fp32 numerics
#define FMA2(d, a, b) asm("fma.rn.f32x2 %0, %1, %2, %0;" : "+l"(d) : "l"(a), "l"(b))

__device__ __forceinline__ void acc_add(float4& a, float4 v) {
    a.x += v.x; a.y += v.y; a.z += v.z; a.w += v.w;
}

// ---------------- init: zero histogram + dtype probe ---------------------------
__global__ void k_init(const int* __restrict__ ei32) {
    if (blockIdx.x < 196) {
        int i = blockIdx.x * 256 + threadIdx.x;
        if (i < N_NODES) g_deg[i] = 0;
        return;
    }
    __shared__ int s_any;
    if (threadIdx.x == 0) s_any = 0;
    __syncthreads();
    int any = 0;
    for (int s = threadIdx.x; s < 4096; s += 256) {
        int i = s * 195;
        if (ei32[2 * i + 1] != 0) any = 1;
    }
    if (any) atomicOr(&s_any, 1);
    __syncthreads();
    if (threadIdx.x == 0) g_is64 = (s_any == 0);
}

// ---------------- repack edges + histogram ------------------------------------
__global__ void k_prep(const int* __restrict__ ei32) {
    int e = blockIdx.x * 256 + threadIdx.x;
    if (e >= N_EDGES) return;
    int2 p;
    if (g_is64) {
        p.x = ei32[2 * e];
        p.y = ei32[2 * (N_EDGES + e)];
    } else {
        p.x = ei32[e];
        p.y = ei32[N_EDGES + e];
    }
    g_srcdst[e] = p;
    atomicAdd(&g_deg[p.y], 1);
}

// ---------------- parallel scan (3 phases) -------------------------------------
__global__ void k_scan_a() {
    __shared__ int s[256];
    int i = blockIdx.x * 256 + threadIdx.x;
    s[threadIdx.x] = (i < N_NODES) ? g_deg[i] : 0;
    __syncthreads();
#pragma unroll
    for (int o = 128; o > 0; o >>= 1) {
        if (threadIdx.x < o) s[threadIdx.x] += s[threadIdx.x + o];
        __syncthreads();
    }
    if (threadIdx.x == 0) g_part[blockIdx.x] = s[0];
}

__global__ void k_scan_b() {
    __shared__ int s[256];
    int t = threadIdx.x;
    int v = (t < 196) ? g_part[t] : 0;
    s[t] = v;
    __syncthreads();
#pragma unroll
    for (int o = 1; o < 256; o <<= 1) {
        int u = (t >= o) ? s[t - o] : 0;
        __syncthreads();
        s[t] += u;
        __syncthreads();
    }
    g_part[t] = s[t] - v;
}

__global__ void k_scan_c() {
    __shared__ int s[256];
    int t = threadIdx.x;
    int i = blockIdx.x * 256 + t;
    int v = (i < N_NODES) ? g_deg[i] : 0;
    s[t] = v;
    __syncthreads();
#pragma unroll
    for (int o = 1; o < 256; o <<= 1) {
        int u = (t >= o) ? s[t - o] : 0;
        __syncthreads();
        s[t] += u;
        __syncthreads();
    }
    int excl = g_part[blockIdx.x] + s[t] - v;
    if (i < N_NODES) {
        g_off[i] = excl;
        g_pos[i] = excl;
        if (i == N_NODES - 1) g_off[N_NODES] = excl + v;
    }
}

// ---------------- CSR fill ------------------------------------------------------
__global__ void k_fill() {
    int e = blockIdx.x * 256 + threadIdx.x;
    if (e >= N_EDGES) return;
    int2 sd = g_srcdst[e];
    int slot = atomicAdd(&g_pos[sd.y], 1);
    g_csr[slot] = sd.x;
}

// ---------------- GEMM1 fused: g_cat[r][0:192] = x[r] @ [Wl1|Wr1|Wlin_top] ------
// 64 rows x 192 cols per block; 256 threads = 16 rg x 16 cg;
// thread = 4 rows x 12 cols (halved smem weight traffic vs 2-row tile).
__global__ void __launch_bounds__(256, 2) k_gemm1(const float* __restrict__ x,
                        const float* __restrict__ Wl1,
                        const float* __restrict__ Wr1,
                        const float* __restrict__ Wlin) {
    extern __shared__ float sm[];
    float* xs = sm;               // [64][129]
    float* ws = sm + 64 * 129;    // [64][192]  (one K-chunk of weights)

    int row0 = blockIdx.x * 64;
    int t = threadIdx.x;

    for (int i = t; i < 64 * 32; i += 256) {
        int m = i >> 5, kc = i & 31;
        int r = row0 + m;
        float4 v = (r < N_NODES) ? ((const float4*)x)[r * 32 + kc]
                                 : make_float4(0.f, 0.f, 0.f, 0.f);
        float* d = xs + m * 129 + kc * 4;
        d[0] = v.x; d[1] = v.y; d[2] = v.z; d[3] = v.w;
    }

    const float4* wl1 = (const float4*)Wl1;
    const float4* wr1 = (const float4*)Wr1;
    const float4* wli = (const float4*)Wlin;

    int rg = t >> 4, cg = t & 15;           // 16 row groups x 16 col groups
    const float* xr0 = xs + (4 * rg) * 129;
    unsigned long long acc[24] = {};        // 4 rows x 6 f32x2 each

    for (int kt = 0; kt < 2; kt++) {
        if (kt) __syncthreads();
        for (int i = t; i < 64 * 48; i += 256) {
            int k = i / 48, c = i % 48;
            int kk = kt * 64 + k;
            float4 v = (c < 16) ? wl1[kk * 16 + c]
                     : (c < 32) ? wr1[kk * 16 + (c - 16)]
                                : wli[kk * 16 + (c - 32)];
            ((float4*)(ws + k * 192))[c] = v;
        }
        __syncthreads();

        const float* xk = xr0 + kt * 64;
#pragma unroll 2
        for (int k = 0; k < 64; k++) {
            unsigned long long a0 = pack2(xk[k]);
            unsigned long long a1 = pack2(xk[k + 129]);
            unsigned long long a2 = pack2(xk[k + 2 * 129]);
            unsigned long long a3 = pack2(xk[k + 3 * 129]);
            const ulonglong2* wp = (const ulonglong2*)(ws + k * 192 + cg * 12);
            ulonglong2 w0 = wp[0], w1 = wp[1], w2 = wp[2];
            FMA2(acc[0],  a0, w0.x); FMA2(acc[1],  a0, w0.y);
            FMA2(acc[2],  a0, w1.x); FMA2(acc[3],  a0, w1.y);
            FMA2(acc[4],  a0, w2.x); FMA2(acc[5],  a0, w2.y);
            FMA2(acc[6],  a1, w0.x); FMA2(acc[7],  a1, w0.y);
            FMA2(acc[8],  a1, w1.x); FMA2(acc[9],  a1, w1.y);
            FMA2(acc[10], a1, w2.x); FMA2(acc[11], a1, w2.y);
            FMA2(acc[12], a2, w0.x); FMA2(acc[13], a2, w0.y);
            FMA2(acc[14], a2, w1.x); FMA2(acc[15], a2, w1.y);
            FMA2(acc[16], a2, w2.x); FMA2(acc[17], a2, w2.y);
            FMA2(acc[18], a3, w0.x); FMA2(acc[19], a3, w0.y);
            FMA2(acc[20], a3, w1.x); FMA2(acc[21], a3, w1.y);
            FMA2(acc[22], a3, w2.x); FMA2(acc[23], a3, w2.y);
        }
    }

#pragma unroll
    for (int i = 0; i < 4; i++) {
        int r = row0 + 4 * rg + i;
        if (r < N_NODES) {
            float* f = (float*)(acc + 6 * i);       // 12 floats
            float4* o = (float4*)(g_cat + r * 192 + cg * 12);
            o[0] = make_float4(f[0], f[1], f[2],  f[3]);
            o[1] = make_float4(f[4], f[5], f[6],  f[7]);
            o[2] = make_float4(f[8], f[9], f[10], f[11]);
        }
    }
}

// ---------------- gather1 + node1 epilogue -------------------------------------
__global__ void k_gather1(const float* __restrict__ bl1) {
    int idx = blockIdx.x * 256 + threadIdx.x;   // exactly N*16 threads
    int node = idx >> 4, j = idx & 15;
    int beg = g_off[node], end = g_off[node + 1];
    const float4* cat4 = (const float4*)g_cat;

    float4 acc = make_float4(0.f, 0.f, 0.f, 0.f);
    int e = beg;
    for (; e + 4 <= end; e += 4) {
        int s0 = g_csr[e], s1 = g_csr[e + 1], s2 = g_csr[e + 2], s3 = g_csr[e + 3];
        float4 v0 = __ldg(cat4 + s0 * 48 + j);
        float4 v1 = __ldg(cat4 + s1 * 48 + j);
        float4 v2 = __ldg(cat4 + s2 * 48 + j);
        float4 v3 = __ldg(cat4 + s3 * 48 + j);
        acc_add(acc, v0); acc_add(acc, v1); acc_add(acc, v2); acc_add(acc, v3);
    }
    for (; e < end; e++) {
        int src = g_csr[e];
        acc_add(acc, __ldg(cat4 + src * 48 + j));
    }

    float inv = 1.0f / fmaxf((float)(end - beg), 1.0f);
    float4 b  = ((const float4*)bl1)[j];
    float4 xr = cat4[node * 48 + 16 + j];
    float4 v;
    v.x = acc.x * inv + b.x + xr.x;
    v.y = acc.y * inv + b.y + xr.y;
    v.z = acc.z * inv + b.z + xr.z;
    v.w = acc.w * inv + b.w + xr.w;
    float ss = v.x * v.x + v.y * v.y + v.z * v.z + v.w * v.w;
    ss += __shfl_xor_sync(0xffffffffu, ss, 8);
    ss += __shfl_xor_sync(0xffffffffu, ss, 4);
    ss += __shfl_xor_sync(0xffffffffu, ss, 2);
    ss += __shfl_xor_sync(0xffffffffu, ss, 1);
    float sc = 1.0f / fmaxf(sqrtf(ss), 1e-12f);
    float4 h;
    h.x = fmaxf(v.x * sc, 0.f);
    h.y = fmaxf(v.y * sc, 0.f);
    h.z = fmaxf(v.z * sc, 0.f);
    h.w = fmaxf(v.w * sc, 0.f);
    ((float4*)g_hidden)[node * 16 + j] = h;
}

// ---------------- GEMM2 (fused): h = relu(xw + hidden@Wh + blin);
//                  z = h@Wl2 ; hr = h@Wr2.  2 rows/thread both phases.
__global__ void __launch_bounds__(256, 2) k_gemm2(const float* __restrict__ Wlin,
                        const float* __restrict__ blin,
                        const float* __restrict__ Wl2,
                        const float* __restrict__ Wr2) {
    extern __shared__ float sm[];
    float* hd = sm;                 // [64][65]
    float* wh = hd + 64 * 65;       // [64][64]
    float* hs = wh + 64 * 64;       // [64][65]
    float* wc = hs + 64 * 65;       // [64][80]

    int row0 = blockIdx.x * 64;
    int t = threadIdx.x;

    for (int i = t; i < 64 * 16; i += 256) {
        int m = i >> 4, kc = i & 15;
        int r = row0 + m;
        float4 v = (r < N_NODES) ? ((const float4*)g_hidden)[r * 16 + kc]
                                 : make_float4(0.f, 0.f, 0.f, 0.f);
        float* d = hd + m * 65 + kc * 4;
        d[0] = v.x; d[1] = v.y; d[2] = v.z; d[3] = v.w;
    }
    const float* Wh = Wlin + 128 * 64;
    for (int i = t; i < 64 * 16; i += 256)
        ((float4*)wh)[i] = ((const float4*)Wh)[i];
    for (int i = t; i < 64 * 40; i += 256) {
        int k = i / 40, j = i % 40;
        wc[k * 80 + j]      = Wl2[i];
        wc[k * 80 + 40 + j] = Wr2[i];
    }
    __syncthreads();

    int rg = t >> 3, cg = t & 7;     // 32 row groups x 8 col groups
    int m0 = 2 * rg;                 // 2 rows per thread
    int r0 = row0 + m0;

    // --- phase A: h (64 cols), thread = 2 rows x 8 cols
    {
        unsigned long long acc[8] = {};          // [0..3] row0, [4..7] row1
        const float* h0 = hd + m0 * 65;
        const float* h1 = h0 + 65;
#pragma unroll 4
        for (int k = 0; k < 64; k++) {
            unsigned long long a0 = pack2(h0[k]);
            unsigned long long a1 = pack2(h1[k]);
            const ulonglong2* wp = (const ulonglong2*)(wh + k * 64 + cg * 8);
            ulonglong2 w0 = wp[0], w1 = wp[1];
            FMA2(acc[0], a0, w0.x); FMA2(acc[1], a0, w0.y);
            FMA2(acc[2], a0, w1.x); FMA2(acc[3], a0, w1.y);
            FMA2(acc[4], a1, w0.x); FMA2(acc[5], a1, w0.y);
            FMA2(acc[6], a1, w1.x); FMA2(acc[7], a1, w1.y);
        }
        const float4* bb = (const float4*)(blin + cg * 8);
        float4 bv0 = bb[0], bv1 = bb[1];
#pragma unroll
        for (int i = 0; i < 2; i++) {
            int r = r0 + i;
            float* f = (float*)(acc + 4 * i);    // 8 floats
            float* hout = hs + (m0 + i) * 65 + cg * 8;
            if (r < N_NODES) {
                const float4* xwv = (const float4*)(g_cat + r * 192 + 128 + cg * 8);
                float4 x0 = xwv[0], x1 = xwv[1];
                hout[0] = fmaxf(f[0] + x0.x + bv0.x, 0.f);
                hout[1] = fmaxf(f[1] + x0.y + bv0.y, 0.f);
                hout[2] = fmaxf(f[2] + x0.z + bv0.z, 0.f);
                hout[3] = fmaxf(f[3] + x0.w + bv0.w, 0.f);
                hout[4] = fmaxf(f[4] + x1.x + bv1.x, 0.f);
                hout[5] = fmaxf(f[5] + x1.y + bv1.y, 0.f);
                hout[6] = fmaxf(f[6] + x1.z + bv1.z, 0.f);
                hout[7] = fmaxf(f[7] + x1.w + bv1.w, 0.f);
            } else {
#pragma unroll
                for (int c = 0; c < 8; c++) hout[c] = 0.f;
            }
        }
    }
    __syncthreads();

    // --- phase B: [z | hr] (80 cols), thread = 2 rows x 10 cols
    {
        unsigned long long acc[10] = {};         // [0..4] row0, [5..9] row1
        const float* h0 = hs + m0 * 65;
        const float* h1 = h0 + 65;
#pragma unroll 4
        for (int k = 0; k < 64; k++) {
            unsigned long long a0 = pack2(h0[k]);
            unsigned long long a1 = pack2(h1[k]);
            const unsigned long long* wp =
                (const unsigned long long*)(wc + k * 80 + cg * 10);
            unsigned long long w0 = wp[0], w1 = wp[1], w2 = wp[2],
                               w3 = wp[3], w4 = wp[4];
            FMA2(acc[0], a0, w0); FMA2(acc[1], a0, w1);
            FMA2(acc[2], a0, w2); FMA2(acc[3], a0, w3);
            FMA2(acc[4], a0, w4);
            FMA2(acc[5], a1, w0); FMA2(acc[6], a1, w1);
            FMA2(acc[7], a1, w2); FMA2(acc[8], a1, w3);
            FMA2(acc[9], a1, w4);
        }
        int c0 = (cg & 3) * 10;
        float* base = (cg < 4) ? g_z : g_hr;
#pragma unroll
        for (int i = 0; i < 2; i++) {
            int r = r0 + i;
            if (r < N_NODES) {
                float* f = (float*)(acc + 5 * i);    // 10 floats
                float2* d2 = (float2*)(base + r * 40 + c0);
                d2[0] = make_float2(f[0], f[1]);
                d2[1] = make_float2(f[2], f[3]);
                d2[2] = make_float2(f[4], f[5]);
                d2[3] = make_float2(f[6], f[7]);
                d2[4] = make_float2(f[8], f[9]);
            }
        }
    }
}

// ---------------- gather2 + node2 epilogue -------------------------------------
__global__ void k_gather2(const float* __restrict__ bl2, float* __restrict__ out) {
    int idx = blockIdx.x * 256 + threadIdx.x;   // exactly N*16 threads
    int node = idx >> 4, j = idx & 15;
    int beg = g_off[node], end = g_off[node + 1];
    const float4* z4 = (const float4*)g_z;

    float4 acc = make_float4(0.f, 0.f, 0.f, 0.f);
    if (j < 10) {
        int e = beg;
        for (; e + 4 <= end; e += 4) {
            int s0 = g_csr[e], s1 = g_csr[e + 1], s2 = g_csr[e + 2], s3 = g_csr[e + 3];
            float4 v0 = __ldg(z4 + s0 * 10 + j);
            float4 v1 = __ldg(z4 + s1 * 10 + j);
            float4 v2 = __ldg(z4 + s2 * 10 + j);
            float4 v3 = __ldg(z4 + s3 * 10 + j);
            acc_add(acc, v0); acc_add(acc, v1); acc_add(acc, v2); acc_add(acc, v3);
        }
        for (; e < end; e++) {
            int src = g_csr[e];
            acc_add(acc, __ldg(z4 + src * 10 + j));
        }
    }
    float inv = 1.0f / fmaxf((float)(end - beg), 1.0f);
    float4 v = make_float4(0.f, 0.f, 0.f, 0.f);
    if (j < 10) {
        float4 b  = ((const float4*)bl2)[j];
        float4 hr = ((const float4*)g_hr)[node * 10 + j];
        v.x = acc.x * inv + b.x + hr.x;
        v.y = acc.y * inv + b.y + hr.y;
        v.z = acc.z * inv + b.z + hr.z;
        v.w = acc.w * inv + b.w + hr.w;
    }
    float ss = v.x * v.x + v.y * v.y + v.z * v.z + v.w * v.w;
    ss += __shfl_xor_sync(0xffffffffu, ss, 8);
    ss += __shfl_xor_sync(0xffffffffu, ss, 4);
    ss += __shfl_xor_sync(0xffffffffu, ss, 2);
    ss += __shfl_xor_sync(0xffffffffu, ss, 1);
    float sc = 1.0f / fmaxf(sqrtf(ss), 1e-12f);
    if (j < 10) {
        float4* op = (float4*)(out + node * 40 + j * 4);
        *op = make_float4(v.x * sc, v.y * sc, v.z * sc, v.w * sc);
    }
}

// ---------------- launch -----------------------------------------------------
static cudaStream_t g_s2 = 0;
static cudaEvent_t  g_evA = 0, g_evB = 0;

extern "C" void kernel_launch(void* const* d_in, const int* in_sizes, int n_in,
                              void* d_out, int out_size) {
    const float* x    = (const float*)d_in[0];
    const int*   ei32 = (const int*)d_in[1];
    const float* Wl1  = (const float*)d_in[2];
    const float* bl1  = (const float*)d_in[3];
    const float* Wr1  = (const float*)d_in[4];
    const float* Wlin = (const float*)d_in[5];
    const float* blin = (const float*)d_in[6];
    const float* Wl2  = (const float*)d_in[7];
    const float* bl2  = (const float*)d_in[8];
    const float* Wr2  = (const float*)d_in[9];
    float* out = (float*)d_out;

    if (!g_s2) {
        cudaStreamCreateWithFlags(&g_s2, cudaStreamNonBlocking);
        cudaEventCreateWithFlags(&g_evA, cudaEventDisableTiming);
        cudaEventCreateWithFlags(&g_evB, cudaEventDisableTiming);
    }

    const int SMEM1 = (64 * 129 + 64 * 192) * 4;                      // 82,176 B
    const int SMEM2 = (64 * 65 + 64 * 64 + 64 * 65 + 64 * 80) * 4;    // 70,144 B
    cudaFuncSetAttribute(k_gemm1, cudaFuncAttributeMaxDynamicSharedMemorySize, SMEM1);
    cudaFuncSetAttribute(k_gemm2, cudaFuncAttributeMaxDynamicSharedMemorySize, SMEM2);

    // fork: CSR build chain on g_s2, concurrent with gemm1 on the main stream
    k_init<<<197, 256>>>(ei32);
    cudaEventRecord(g_evA, 0);
    cudaStreamWaitEvent(g_s2, g_evA, 0);

    k_prep<<<3125, 256, 0, g_s2>>>(ei32);
    k_scan_a<<<196, 256, 0, g_s2>>>();
    k_scan_b<<<1, 256, 0, g_s2>>>();
    k_scan_c<<<196, 256, 0, g_s2>>>();
    k_fill<<<3125, 256, 0, g_s2>>>();
    cudaEventRecord(g_evB, g_s2);

    k_gemm1<<<782, 256, SMEM1>>>(x, Wl1, Wr1, Wlin);   // overlapped with CSR

    cudaStreamWaitEvent(0, g_evB, 0);                  // join
    k_gather1<<<3125, 256>>>(bl1);
    k_gemm2<<<782, 256, SMEM2>>>(Wlin, blin, Wl2, Wr2);
    k_gather2<<<3125, 256>>>(bl2, out);
}